// round 13
// baseline (speedup 1.0000x reference)
#include <cuda_runtime.h>
#include <math.h>

#define BSZ 8
#define LSEQ 512
#define DM 256
#define NH 8
#define DH 32
#define DS 30

#define TQ 8       // q rows per CTA; warp w is head w AND q-row w (role switch)
#define TK 32
#define NKT (LSEQ / TK)
#define NTHREADS 256

#define ST_ROW 960            // linear [k*30+s] per q-row
#define PT_Q 289              // Sqk [q][k*9+h]
#define P2R 33                // p rows [(q*8+h)][33]

// ---- attn dynamic smem layout (float offsets), total 18230 fl = 72.9 KB ----
#define OFF_QS  0              // [8h][8q][32]  = 2048
#define OFF_QW  2048           // [8h][8q][32]  = 2048 (qwsk, s padded 30->32 zeros)
#define OFF_ST  4096           // 8q * 960      = 7680 (warp-local rows)
#define OFF_PT  11776          // 8 * 289       = 2312 (PS overlays this in epilogue)
#define OFF_P2  14088          // 64 * 33       = 2112
#define OFF_WSK 16200          // 960
#define OFF_WSV 17160          // 30*33 = 990
#define OFF_LS  18150          // 80
#define SMEM_FLOATS 18230
#define SMEM_BYTES (SMEM_FLOATS * 4)

// scratch: qh, kh, vh, ctx, ktr (1M fl each) + scores0 (2M fl)
__device__ float g_scratch[5 * BSZ * LSEQ * DM + BSZ * LSEQ * LSEQ];
__device__ int g_mask_is_byte;

// cp.async 16B helper
__device__ __forceinline__ void cp_async16(void* smem_dst, const void* gmem_src)
{
    unsigned saddr = (unsigned)__cvta_generic_to_shared(smem_dst);
    asm volatile("cp.async.cg.shared.global [%0], [%1], 16;" :: "r"(saddr), "l"(gmem_src));
}
__device__ __forceinline__ void cp_async_commit() { asm volatile("cp.async.commit_group;"); }
__device__ __forceinline__ void cp_async_wait_all() { asm volatile("cp.async.wait_group 0;"); }

// ---------------------------------------------------------------------------
__global__ void detect_mask_kernel(const unsigned char* __restrict__ m, int nbytes)
{
    __shared__ int any;
    if (threadIdx.x == 0) any = 0;
    __syncthreads();
    int local = 0;
    for (int i = threadIdx.x; i < nbytes; i += blockDim.x)
        if ((i & 3) != 0 && m[i] != 0) local = 1;
    if (local) atomicOr(&any, 1);
    __syncthreads();
    if (threadIdx.x == 0) g_mask_is_byte = any;
}

// ---------------------------------------------------------------------------
// K transpose: ktr[b][n][m] = kh[b*512+m][n]
// ---------------------------------------------------------------------------
__global__ void __launch_bounds__(256) transpose_k(
    const float* __restrict__ kh, float* __restrict__ ktr)
{
    __shared__ float t[32][33];
    const int b = blockIdx.z;
    const int m0 = blockIdx.x * 32, n0 = blockIdx.y * 32;
    const int tx = threadIdx.x, ty = threadIdx.y;

    for (int r = ty; r < 32; r += 8)
        t[r][tx] = kh[(size_t)(b * LSEQ + m0 + r) * DM + n0 + tx];
    __syncthreads();
    for (int r = ty; r < 32; r += 8)
        ktr[(size_t)b * DM * LSEQ + (size_t)(n0 + r) * LSEQ + m0 + tx] = t[tx][r];
}

// ---------------------------------------------------------------------------
// SGEMM 128x128 tile, 256 threads, 8x8 microtile, double-buffered.
// ---------------------------------------------------------------------------
__device__ __forceinline__ void gemm128_body(
    const float* __restrict__ A, const float* __restrict__ W,
    const float* __restrict__ bias, float* __restrict__ C, float scale,
    int m0, int n0)
{
    __shared__ float As[2][8][128];
    __shared__ float Bs[2][8][128];

    const int tid = threadIdx.x;
    const int am = tid >> 1;
    const int ak = (tid & 1) * 4;
    const int br = tid >> 5;
    const int bc = (tid & 31) * 4;
    const int tx = tid & 15, ty = tid >> 4;

    float4 av = *reinterpret_cast<const float4*>(&A[(size_t)(m0 + am) * 256 + ak]);
    float4 bv = *reinterpret_cast<const float4*>(&W[(size_t)br * 256 + n0 + bc]);

    As[0][ak + 0][am] = av.x; As[0][ak + 1][am] = av.y;
    As[0][ak + 2][am] = av.z; As[0][ak + 3][am] = av.w;
    *reinterpret_cast<float4*>(&Bs[0][br][bc]) = bv;
    __syncthreads();

    float acc[8][8] = {};
    int buf = 0;

    for (int k0 = 0; k0 < 256; k0 += 8) {
        const bool more = (k0 + 8 < 256);
        if (more) {
            av = *reinterpret_cast<const float4*>(&A[(size_t)(m0 + am) * 256 + k0 + 8 + ak]);
            bv = *reinterpret_cast<const float4*>(&W[(size_t)(k0 + 8 + br) * 256 + n0 + bc]);
        }
#pragma unroll
        for (int kk = 0; kk < 8; kk++) {
            float a[8], b[8];
            *reinterpret_cast<float4*>(&a[0]) = *reinterpret_cast<const float4*>(&As[buf][kk][ty * 8]);
            *reinterpret_cast<float4*>(&a[4]) = *reinterpret_cast<const float4*>(&As[buf][kk][ty * 8 + 4]);
            *reinterpret_cast<float4*>(&b[0]) = *reinterpret_cast<const float4*>(&Bs[buf][kk][tx * 8]);
            *reinterpret_cast<float4*>(&b[4]) = *reinterpret_cast<const float4*>(&Bs[buf][kk][tx * 8 + 4]);
#pragma unroll
            for (int i = 0; i < 8; i++)
#pragma unroll
                for (int j = 0; j < 8; j++) acc[i][j] += a[i] * b[j];
        }
        if (more) {
            buf ^= 1;
            As[buf][ak + 0][am] = av.x; As[buf][ak + 1][am] = av.y;
            As[buf][ak + 2][am] = av.z; As[buf][ak + 3][am] = av.w;
            *reinterpret_cast<float4*>(&Bs[buf][br][bc]) = bv;
            __syncthreads();
        }
    }

    float bb[8];
#pragma unroll
    for (int j = 0; j < 8; j++) bb[j] = bias[n0 + tx * 8 + j];
#pragma unroll
    for (int i = 0; i < 8; i++) {
        float4 c0, c1;
        c0.x = (acc[i][0] + bb[0]) * scale; c0.y = (acc[i][1] + bb[1]) * scale;
        c0.z = (acc[i][2] + bb[2]) * scale; c0.w = (acc[i][3] + bb[3]) * scale;
        c1.x = (acc[i][4] + bb[4]) * scale; c1.y = (acc[i][5] + bb[5]) * scale;
        c1.z = (acc[i][6] + bb[6]) * scale; c1.w = (acc[i][7] + bb[7]) * scale;
        float* cp = &C[(size_t)(m0 + ty * 8 + i) * 256 + n0 + tx * 8];
        reinterpret_cast<float4*>(cp)[0] = c0;
        reinterpret_cast<float4*>(cp)[1] = c1;
    }
}

__global__ void __launch_bounds__(256) gemm128(
    const float* __restrict__ A, const float* __restrict__ W,
    const float* __restrict__ bias, float* __restrict__ C, float scale)
{
    gemm128_body(A, W, bias, C, scale, blockIdx.y * 128, blockIdx.x * 128);
}

__global__ void __launch_bounds__(256) qkv_gemm(
    const float* __restrict__ Aq, const float* __restrict__ Ak, const float* __restrict__ Av,
    const float* __restrict__ Wq, const float* __restrict__ Wk, const float* __restrict__ Wv,
    const float* __restrict__ bq, const float* __restrict__ bk, const float* __restrict__ bv,
    float* __restrict__ Cq, float* __restrict__ Ck, float* __restrict__ Cv)
{
    const float *A, *W, *bias; float* C; float scale;
    if (blockIdx.z == 0)      { A = Aq; W = Wq; bias = bq; C = Cq; scale = 0.17677669529663688f; }
    else if (blockIdx.z == 1) { A = Ak; W = Wk; bias = bk; C = Ck; scale = 1.0f; }
    else                      { A = Av; W = Wv; bias = bv; C = Cv; scale = 1.0f; }
    gemm128_body(A, W, bias, C, scale, blockIdx.y * 128, blockIdx.x * 128);
}

// ---------------------------------------------------------------------------
// Fused attention, fixed-max softmax, role-switching warps, 3 CTAs/SM:
//   ST rows are warp-local (staged, read in BIAS and ACC-PS by the same warp)
//   and staged via cp.async (register-free). Low-register phase loops.
// ---------------------------------------------------------------------------
__global__ void __launch_bounds__(NTHREADS, 3) attn_kernel(
    const float* __restrict__ qh, const float* __restrict__ ktr, const float* __restrict__ vh,
    const float* __restrict__ st_g, const void* __restrict__ kmask_raw,
    const float* __restrict__ wsk, const float* __restrict__ wsv, const float* __restrict__ bsv,
    float* __restrict__ ctx, float* __restrict__ scores0)
{
    extern __shared__ float sm[];
    float* QS  = sm + OFF_QS;
    float* QW  = sm + OFF_QW;
    float* ST  = sm + OFF_ST;
    float* PT  = sm + OFF_PT;
    float* P2  = sm + OFF_P2;
    float* WSK = sm + OFF_WSK;
    float* WSV = sm + OFF_WSV;
    float* LS  = sm + OFF_LS;
    float* PS  = sm + OFF_PT;   // overlays PT (dead after last BIAS)

    const int tid = threadIdx.x;
    const int w = tid >> 5, lane = tid & 31;
    const int aq = lane >> 2, aoct = lane & 3;    // ACC-V / epilogue lane identity
    const int b = blockIdx.x >> 6;
    const int q0 = (blockIdx.x & 63) * TQ;
    const int mask_is_byte = g_mask_is_byte;
    const unsigned char* km8 = (const unsigned char*)kmask_raw;
    const int* km32 = (const int*)kmask_raw;

    // struct staging: warp w stages q-row w, linear layout, cp.async
    const float* st_qrow = st_g + (((size_t)b * LSEQ + q0 + w) * LSEQ) * DS;
    float* st_dst = ST + w * ST_ROW;

    const float* ktb = ktr + (size_t)b * DM * LSEQ + (size_t)(w * DH) * LSEQ;

    // ---- issue cp.async for tile 0 immediately ----
    {
        const float* src = st_qrow;   // k0 = 0
#pragma unroll
        for (int c = lane; c < 240; c += 32)
            cp_async16(st_dst + c * 4, src + c * 4);
        cp_async_commit();
    }

    // ---- init: QS, WSK, WSV, zero QW ----
    {
        const float4* qg4 = reinterpret_cast<const float4*>(qh + ((size_t)b * LSEQ + q0) * DM);
        for (int f = tid; f < TQ * DM / 4; f += NTHREADS) {
            int q = f >> 6, c4 = f & 63;
            float4 v = qg4[f];
            int hh = c4 >> 3, d = (c4 & 7) * 4;
            float* dst = &QS[(hh * TQ + q) * 32 + d];
            dst[0] = v.x; dst[1] = v.y; dst[2] = v.z; dst[3] = v.w;
        }
    }
    for (int i = tid; i < DS * DH; i += NTHREADS) WSK[i] = wsk[i];
    for (int i = tid; i < DS * DH; i += NTHREADS) {
        int s = i >> 5, d = i & 31;
        WSV[s * 33 + d] = wsv[i];
    }
    for (int i = tid; i < NH * TQ * 32; i += NTHREADS) QW[i] = 0.f;
    __syncthreads();

    // qwsk[h,q,s] = sum_d QS[h,q,d] * wsk[s,d]
    for (int i = tid; i < NH * TQ * DS; i += NTHREADS) {
        int hh = i / (TQ * DS);
        int r = i - hh * (TQ * DS);
        int q = r / DS;
        int s = r - q * DS;
        const float* qp = &QS[(hh * TQ + q) * 32];
        const float* wp = &WSK[s * 32];
        float a = 0.f;
#pragma unroll
        for (int d = 0; d < 32; d++) a += qp[d] * wp[d];
        QW[(hh * TQ + q) * 32 + s] = a;
    }
    cp_async_wait_all();      // tile-0 struct data (warp-local)
    __syncthreads();          // QW visible to all

    float acc[8], psp[8];
    float lsum = 0.f;
#pragma unroll
    for (int i = 0; i < 8; i++) { acc[i] = 0.f; psp[i] = 0.f; }

    for (int kt = 0; kt < NKT; kt++) {
        const int k0 = kt * TK;

        // ======== QK phase: warp = head w, lane = k (d4-outer, low regs) ========
        {
            float sacc[8];
#pragma unroll
            for (int q = 0; q < 8; q++) sacc[q] = 0.f;
            const float* kp = ktb + k0 + lane;
#pragma unroll
            for (int d4 = 0; d4 < 8; d4++) {
                float k0r = kp[(size_t)(d4 * 4 + 0) * LSEQ];
                float k1r = kp[(size_t)(d4 * 4 + 1) * LSEQ];
                float k2r = kp[(size_t)(d4 * 4 + 2) * LSEQ];
                float k3r = kp[(size_t)(d4 * 4 + 3) * LSEQ];
#pragma unroll
                for (int q = 0; q < 8; q++) {
                    float4 qd = reinterpret_cast<const float4*>(&QS[(w * TQ + q) * 32])[d4];
                    sacc[q] += qd.x * k0r + qd.y * k1r + qd.z * k2r + qd.w * k3r;
                }
            }
#pragma unroll
            for (int q = 0; q < 8; q++)
                PT[q * PT_Q + lane * 9 + w] = sacc[q];
        }
        __syncthreads();   // (1) Sqk visible (cp.async for this tile already waited)

        // ======== BIAS phase: warp = q-row w, lane = k (s4-outer, low regs) ====
        {
            const int midx = b * LSEQ + k0 + lane;
            const bool masked = mask_is_byte ? (km8[midx] != 0) : (km32[midx] != 0);

            const float* stq = ST + w * ST_ROW + lane * DS;   // lane's k row (linear)
            float bias[8];
#pragma unroll
            for (int h2 = 0; h2 < 8; h2++) bias[h2] = 0.f;
#pragma unroll
            for (int s4 = 0; s4 < 7; s4++) {
                float v0 = stq[s4 * 4 + 0];
                float v1 = stq[s4 * 4 + 1];
                float v2 = stq[s4 * 4 + 2];
                float v3 = stq[s4 * 4 + 3];
#pragma unroll
                for (int h2 = 0; h2 < 8; h2++) {
                    float4 ww = reinterpret_cast<const float4*>(&QW[(h2 * TQ + w) * 32])[s4];
                    bias[h2] += ww.x * v0 + ww.y * v1 + ww.z * v2 + ww.w * v3;
                }
            }
            {
                float v0 = stq[28], v1 = stq[29];
#pragma unroll
                for (int h2 = 0; h2 < 8; h2++)
                    bias[h2] += QW[(h2 * TQ + w) * 32 + 28] * v0
                              + QW[(h2 * TQ + w) * 32 + 29] * v1;
            }
            float pq0 = 0.f;
#pragma unroll
            for (int h2 = 0; h2 < 8; h2++) {
                float sc = PT[w * PT_Q + lane * 9 + h2] + bias[h2];
                float p = masked ? 0.f : __expf(sc);
                if (h2 == 0) pq0 = p;
                P2[(w * 8 + h2) * P2R + lane] = p;
            }
            scores0[((size_t)(b * LSEQ + q0 + w)) * LSEQ + k0 + lane] = pq0;
        }
        __syncthreads();   // (2) p visible

        // ======== ACC-V: warp = head w, lane = (aq, aoct) ========
        {
            const float* vbase = vh + ((size_t)(b * LSEQ + k0)) * DM + w * DH + aoct * 8;
            const float* prow = &P2[(aq * 8 + w) * P2R];
#pragma unroll 4
            for (int k = 0; k < TK; k++) {
                float p = prow[k];
                float4 v0 = *reinterpret_cast<const float4*>(vbase + (size_t)k * DM);
                float4 v1 = *reinterpret_cast<const float4*>(vbase + (size_t)k * DM + 4);
                acc[0] += p * v0.x; acc[1] += p * v0.y; acc[2] += p * v0.z; acc[3] += p * v0.w;
                acc[4] += p * v1.x; acc[5] += p * v1.y; acc[6] += p * v1.z; acc[7] += p * v1.w;
                lsum += p;
            }
        }

        // ======== ACC-PS: warp = q-row w, lane = s ========
        if (lane < DS) {
            const float* stq2 = ST + w * ST_ROW + lane;
            const float* pbase = &P2[(w * 8) * P2R];
#pragma unroll 4
            for (int k = 0; k < TK; k++) {
                float svk = stq2[k * DS];
#pragma unroll
                for (int h2 = 0; h2 < NH; h2++)
                    psp[h2] += pbase[h2 * P2R + k] * svk;
            }
        }

        __syncthreads();   // (3) done reading ST/P2

        // issue cp.async for next tile (overlaps next QK; warp-local data)
        if (kt + 1 < NKT) {
            const float* src = st_qrow + (size_t)(k0 + TK) * DS;
#pragma unroll
            for (int c = lane; c < 240; c += 32)
                cp_async16(st_dst + c * 4, src + c * 4);
            cp_async_commit();
            cp_async_wait_all();   // cheap: next consumer is own warp's BIAS, after QK
        }
    }

    // ---- epilogue ----
    if (aoct == 0) LS[aq * 9 + w] = lsum;        // lsum for (h=w, q=aq)
    __syncthreads();                              // PT dead -> PS overlay safe
    if (lane < DS) {
#pragma unroll
        for (int h2 = 0; h2 < NH; h2++)
            PS[(w * 8 + h2) * P2R + lane] = psp[h2];   // ps for (q=w, h2, s=lane)
    }
    __syncthreads();

    // final: warp = head w, lane = (aq, aoct)
    {
        float linv = 1.f / LS[aq * 9 + w];
        float c[8];
#pragma unroll
        for (int j = 0; j < 8; j++) c[j] = acc[j];

        const float* psrow = &PS[(aq * 8 + w) * P2R];
#pragma unroll
        for (int s = 0; s < DS; s++) {
            float pv = psrow[s];
            const float* wr = &WSV[s * 33 + aoct * 8];
#pragma unroll
            for (int j = 0; j < 8; j++) c[j] += pv * wr[j];
        }
#pragma unroll
        for (int j = 0; j < 8; j++) c[j] = c[j] * linv + bsv[aoct * 8 + j];

        float* outp = &ctx[((size_t)(b * LSEQ + q0 + aq)) * DM + w * DH + aoct * 8];
        float4 o0 = { c[0], c[1], c[2], c[3] };
        float4 o1 = { c[4], c[5], c[6], c[7] };
        reinterpret_cast<float4*>(outp)[0] = o0;
        reinterpret_cast<float4*>(outp)[1] = o1;
    }
}

// ---------------------------------------------------------------------------
__global__ void __launch_bounds__(256) normalize_rows(
    const float* __restrict__ P, float* __restrict__ O)
{
    const int row = blockIdx.x;
    const float* s = P + (size_t)row * LSEQ;
    float* o = O + (size_t)row * LSEQ;
    const int t = threadIdx.x;

    float a = s[t], b = s[t + 256];
    float sum = a + b;
    __shared__ float red[8];
#pragma unroll
    for (int off = 16; off; off >>= 1) sum += __shfl_xor_sync(0xffffffffu, sum, off);
    if ((t & 31) == 0) red[t >> 5] = sum;
    __syncthreads();
    float sAll = 0.f;
#pragma unroll
    for (int i = 0; i < 8; i++) sAll += red[i];
    float inv = 1.f / sAll;
    o[t] = a * inv;
    o[t + 256] = b * inv;
}

// ---------------------------------------------------------------------------
extern "C" void kernel_launch(void* const* d_in, const int* in_sizes, int n_in,
                              void* d_out, int out_size)
{
    const float* key   = (const float*)d_in[0];
    const float* value = (const float*)d_in[1];
    const float* query = (const float*)d_in[2];

    const float* structure;
    const void*  kmaskp;
    if (in_sizes[3] == BSZ * LSEQ) {
        kmaskp    = d_in[3];
        structure = (const float*)d_in[4];
    } else {
        structure = (const float*)d_in[3];
        kmaskp    = d_in[4];
    }

    const float* wq  = (const float*)d_in[5];
    const float* bq  = (const float*)d_in[6];
    const float* wk  = (const float*)d_in[7];
    const float* bk  = (const float*)d_in[8];
    const float* wv  = (const float*)d_in[9];
    const float* bv  = (const float*)d_in[10];
    const float* wsk = (const float*)d_in[11];
    // d_in[12] = bsk: softmax-invariant, dropped.
    const float* wsv = (const float*)d_in[13];
    const float* bsv = (const float*)d_in[14];
    const float* wf  = (const float*)d_in[15];
    const float* bf  = (const float*)d_in[16];

    float* out = (float*)d_out;
    float* fin = out + (size_t)BSZ * LSEQ * DM;

    float* scratch = nullptr;
    cudaGetSymbolAddress((void**)&scratch, g_scratch);
    float* qh  = scratch;
    float* kh  = qh + (size_t)BSZ * LSEQ * DM;
    float* vh  = kh + (size_t)BSZ * LSEQ * DM;
    float* ctx = vh + (size_t)BSZ * LSEQ * DM;
    float* ktr = ctx + (size_t)BSZ * LSEQ * DM;
    float* sc0 = ktr + (size_t)BSZ * LSEQ * DM;

    detect_mask_kernel<<<1, 256>>>((const unsigned char*)kmaskp, BSZ * LSEQ);

    qkv_gemm<<<dim3(2, 32, 3), 256>>>(query, key, value,
                                      wq, wk, wv, bq, bk, bv,
                                      qh, kh, vh);

    transpose_k<<<dim3(16, 8, 8), dim3(32, 8)>>>(kh, ktr);

    cudaFuncSetAttribute(attn_kernel, cudaFuncAttributeMaxDynamicSharedMemorySize, SMEM_BYTES);
    attn_kernel<<<BSZ * (LSEQ / TQ), NTHREADS, SMEM_BYTES>>>(
        qh, ktr, vh, structure, kmaskp, wsk, wsv, bsv, ctx, sc0);

    normalize_rows<<<BSZ * LSEQ, 256>>>(sc0, fin);
    gemm128<<<dim3(2, 32), 256>>>(ctx, wf, bf, out, 1.0f);
}

// round 14
// speedup vs baseline: 1.0410x; 1.0410x over previous
#include <cuda_runtime.h>
#include <math.h>

#define BSZ 8
#define LSEQ 512
#define DM 256
#define NH 8
#define DH 32
#define DS 30

#define TQ 8       // q rows per CTA; warp w is head w AND q-row w (role switch)
#define TK 32
#define NKT (LSEQ / TK)
#define NTHREADS 256

#define ST_ROW 960            // linear [k*30+s] per q-row (warp-local)
#define PT_Q 289              // Sqk [q][k*9+h]
#define P2R 33                // p rows [(q*8+h)][33]

// ---- attn dynamic smem layout (float offsets), total 18230 fl = 72.9 KB ----
#define OFF_QS  0              // [8h][8q][32]  = 2048
#define OFF_QW  2048           // [8h][8q][32]  = 2048 (qwsk, s padded 30->32 zeros)
#define OFF_ST  4096           // 8q * 960      = 7680 (warp-local rows)
#define OFF_PT  11776          // 8 * 289       = 2312 (PS overlays this in epilogue)
#define OFF_P2  14088          // 64 * 33       = 2112
#define OFF_WSK 16200          // 960
#define OFF_WSV 17160          // 30*33 = 990
#define OFF_LS  18150          // 80
#define SMEM_FLOATS 18230
#define SMEM_BYTES (SMEM_FLOATS * 4)

// scratch: qh, kh, vh, ctx, ktr (1M fl each) + scores0 (2M fl)
__device__ float g_scratch[5 * BSZ * LSEQ * DM + BSZ * LSEQ * LSEQ];
__device__ int g_mask_is_byte;

// cp.async 16B helper
__device__ __forceinline__ void cp_async16(void* smem_dst, const void* gmem_src)
{
    unsigned saddr = (unsigned)__cvta_generic_to_shared(smem_dst);
    asm volatile("cp.async.cg.shared.global [%0], [%1], 16;" :: "r"(saddr), "l"(gmem_src));
}
__device__ __forceinline__ void cp_async_commit() { asm volatile("cp.async.commit_group;"); }
__device__ __forceinline__ void cp_async_wait_all() { asm volatile("cp.async.wait_group 0;"); }

// ---------------------------------------------------------------------------
__global__ void detect_mask_kernel(const unsigned char* __restrict__ m, int nbytes)
{
    __shared__ int any;
    if (threadIdx.x == 0) any = 0;
    __syncthreads();
    int local = 0;
    for (int i = threadIdx.x; i < nbytes; i += blockDim.x)
        if ((i & 3) != 0 && m[i] != 0) local = 1;
    if (local) atomicOr(&any, 1);
    __syncthreads();
    if (threadIdx.x == 0) g_mask_is_byte = any;
}

// ---------------------------------------------------------------------------
// K transpose: ktr[b][n][m] = kh[b*512+m][n]
// ---------------------------------------------------------------------------
__global__ void __launch_bounds__(256) transpose_k(
    const float* __restrict__ kh, float* __restrict__ ktr)
{
    __shared__ float t[32][33];
    const int b = blockIdx.z;
    const int m0 = blockIdx.x * 32, n0 = blockIdx.y * 32;
    const int tx = threadIdx.x, ty = threadIdx.y;

    for (int r = ty; r < 32; r += 8)
        t[r][tx] = kh[(size_t)(b * LSEQ + m0 + r) * DM + n0 + tx];
    __syncthreads();
    for (int r = ty; r < 32; r += 8)
        ktr[(size_t)b * DM * LSEQ + (size_t)(n0 + r) * LSEQ + m0 + tx] = t[tx][r];
}

// ---------------------------------------------------------------------------
// SGEMM 128x128 tile, 256 threads, 8x8 microtile, double-buffered.
// ---------------------------------------------------------------------------
__device__ __forceinline__ void gemm128_body(
    const float* __restrict__ A, const float* __restrict__ W,
    const float* __restrict__ bias, float* __restrict__ C, float scale,
    int m0, int n0)
{
    __shared__ float As[2][8][128];
    __shared__ float Bs[2][8][128];

    const int tid = threadIdx.x;
    const int am = tid >> 1;
    const int ak = (tid & 1) * 4;
    const int br = tid >> 5;
    const int bc = (tid & 31) * 4;
    const int tx = tid & 15, ty = tid >> 4;

    float4 av = *reinterpret_cast<const float4*>(&A[(size_t)(m0 + am) * 256 + ak]);
    float4 bv = *reinterpret_cast<const float4*>(&W[(size_t)br * 256 + n0 + bc]);

    As[0][ak + 0][am] = av.x; As[0][ak + 1][am] = av.y;
    As[0][ak + 2][am] = av.z; As[0][ak + 3][am] = av.w;
    *reinterpret_cast<float4*>(&Bs[0][br][bc]) = bv;
    __syncthreads();

    float acc[8][8] = {};
    int buf = 0;

    for (int k0 = 0; k0 < 256; k0 += 8) {
        const bool more = (k0 + 8 < 256);
        if (more) {
            av = *reinterpret_cast<const float4*>(&A[(size_t)(m0 + am) * 256 + k0 + 8 + ak]);
            bv = *reinterpret_cast<const float4*>(&W[(size_t)(k0 + 8 + br) * 256 + n0 + bc]);
        }
#pragma unroll
        for (int kk = 0; kk < 8; kk++) {
            float a[8], b[8];
            *reinterpret_cast<float4*>(&a[0]) = *reinterpret_cast<const float4*>(&As[buf][kk][ty * 8]);
            *reinterpret_cast<float4*>(&a[4]) = *reinterpret_cast<const float4*>(&As[buf][kk][ty * 8 + 4]);
            *reinterpret_cast<float4*>(&b[0]) = *reinterpret_cast<const float4*>(&Bs[buf][kk][tx * 8]);
            *reinterpret_cast<float4*>(&b[4]) = *reinterpret_cast<const float4*>(&Bs[buf][kk][tx * 8 + 4]);
#pragma unroll
            for (int i = 0; i < 8; i++)
#pragma unroll
                for (int j = 0; j < 8; j++) acc[i][j] += a[i] * b[j];
        }
        if (more) {
            buf ^= 1;
            As[buf][ak + 0][am] = av.x; As[buf][ak + 1][am] = av.y;
            As[buf][ak + 2][am] = av.z; As[buf][ak + 3][am] = av.w;
            *reinterpret_cast<float4*>(&Bs[buf][br][bc]) = bv;
            __syncthreads();
        }
    }

    float bb[8];
#pragma unroll
    for (int j = 0; j < 8; j++) bb[j] = bias[n0 + tx * 8 + j];
#pragma unroll
    for (int i = 0; i < 8; i++) {
        float4 c0, c1;
        c0.x = (acc[i][0] + bb[0]) * scale; c0.y = (acc[i][1] + bb[1]) * scale;
        c0.z = (acc[i][2] + bb[2]) * scale; c0.w = (acc[i][3] + bb[3]) * scale;
        c1.x = (acc[i][4] + bb[4]) * scale; c1.y = (acc[i][5] + bb[5]) * scale;
        c1.z = (acc[i][6] + bb[6]) * scale; c1.w = (acc[i][7] + bb[7]) * scale;
        float* cp = &C[(size_t)(m0 + ty * 8 + i) * 256 + n0 + tx * 8];
        reinterpret_cast<float4*>(cp)[0] = c0;
        reinterpret_cast<float4*>(cp)[1] = c1;
    }
}

__global__ void __launch_bounds__(256) gemm128(
    const float* __restrict__ A, const float* __restrict__ W,
    const float* __restrict__ bias, float* __restrict__ C, float scale)
{
    gemm128_body(A, W, bias, C, scale, blockIdx.y * 128, blockIdx.x * 128);
}

__global__ void __launch_bounds__(256) qkv_gemm(
    const float* __restrict__ Aq, const float* __restrict__ Ak, const float* __restrict__ Av,
    const float* __restrict__ Wq, const float* __restrict__ Wk, const float* __restrict__ Wv,
    const float* __restrict__ bq, const float* __restrict__ bk, const float* __restrict__ bv,
    float* __restrict__ Cq, float* __restrict__ Ck, float* __restrict__ Cv)
{
    const float *A, *W, *bias; float* C; float scale;
    if (blockIdx.z == 0)      { A = Aq; W = Wq; bias = bq; C = Cq; scale = 0.17677669529663688f; }
    else if (blockIdx.z == 1) { A = Ak; W = Wk; bias = bk; C = Ck; scale = 1.0f; }
    else                      { A = Av; W = Wv; bias = bv; C = Cv; scale = 1.0f; }
    gemm128_body(A, W, bias, C, scale, blockIdx.y * 128, blockIdx.x * 128);
}

// ---------------------------------------------------------------------------
// Fused attention, fixed-max softmax, role-switching warps, 3 CTAs/SM.
// Pipelined cp.async: ST rows are WARP-LOCAL, so the next tile's struct load
// is issued right after ACC-PS (last reader) and waited just before BIAS of
// the next tile — overlap = ACC-V + QK. Only 2 barriers per tile.
// ---------------------------------------------------------------------------
__global__ void __launch_bounds__(NTHREADS, 3) attn_kernel(
    const float* __restrict__ qh, const float* __restrict__ ktr, const float* __restrict__ vh,
    const float* __restrict__ st_g, const void* __restrict__ kmask_raw,
    const float* __restrict__ wsk, const float* __restrict__ wsv, const float* __restrict__ bsv,
    float* __restrict__ ctx, float* __restrict__ scores0)
{
    extern __shared__ float sm[];
    float* QS  = sm + OFF_QS;
    float* QW  = sm + OFF_QW;
    float* ST  = sm + OFF_ST;
    float* PT  = sm + OFF_PT;
    float* P2  = sm + OFF_P2;
    float* WSK = sm + OFF_WSK;
    float* WSV = sm + OFF_WSV;
    float* LS  = sm + OFF_LS;
    float* PS  = sm + OFF_PT;   // overlays PT (dead after last BIAS)

    const int tid = threadIdx.x;
    const int w = tid >> 5, lane = tid & 31;
    const int aq = lane >> 2, aoct = lane & 3;    // ACC-V / epilogue lane identity
    const int b = blockIdx.x >> 6;
    const int q0 = (blockIdx.x & 63) * TQ;
    const int mask_is_byte = g_mask_is_byte;
    const unsigned char* km8 = (const unsigned char*)kmask_raw;
    const int* km32 = (const int*)kmask_raw;

    // struct staging: warp w stages q-row w, linear layout, cp.async (warp-local!)
    const float* st_qrow = st_g + (((size_t)b * LSEQ + q0 + w) * LSEQ) * DS;
    float* st_dst = ST + w * ST_ROW;

    const float* ktb = ktr + (size_t)b * DM * LSEQ + (size_t)(w * DH) * LSEQ;

    // ---- issue cp.async for tile 0 immediately (waited before first BIAS) ----
    {
        const float* src = st_qrow;
#pragma unroll
        for (int c = lane; c < 240; c += 32)
            cp_async16(st_dst + c * 4, src + c * 4);
        cp_async_commit();
    }

    // ---- init: QS, WSK, WSV, zero QW ----
    {
        const float4* qg4 = reinterpret_cast<const float4*>(qh + ((size_t)b * LSEQ + q0) * DM);
        for (int f = tid; f < TQ * DM / 4; f += NTHREADS) {
            int q = f >> 6, c4 = f & 63;
            float4 v = qg4[f];
            int hh = c4 >> 3, d = (c4 & 7) * 4;
            float* dst = &QS[(hh * TQ + q) * 32 + d];
            dst[0] = v.x; dst[1] = v.y; dst[2] = v.z; dst[3] = v.w;
        }
    }
    for (int i = tid; i < DS * DH; i += NTHREADS) WSK[i] = wsk[i];
    for (int i = tid; i < DS * DH; i += NTHREADS) {
        int s = i >> 5, d = i & 31;
        WSV[s * 33 + d] = wsv[i];
    }
    for (int i = tid; i < NH * TQ * 32; i += NTHREADS) QW[i] = 0.f;
    __syncthreads();

    // qwsk[h,q,s] = sum_d QS[h,q,d] * wsk[s,d]
    for (int i = tid; i < NH * TQ * DS; i += NTHREADS) {
        int hh = i / (TQ * DS);
        int r = i - hh * (TQ * DS);
        int q = r / DS;
        int s = r - q * DS;
        const float* qp = &QS[(hh * TQ + q) * 32];
        const float* wp = &WSK[s * 32];
        float a = 0.f;
#pragma unroll
        for (int d = 0; d < 32; d++) a += qp[d] * wp[d];
        QW[(hh * TQ + q) * 32 + s] = a;
    }
    __syncthreads();          // QW visible to all

    float acc[8], psp[8];
    float lsum = 0.f;
#pragma unroll
    for (int i = 0; i < 8; i++) { acc[i] = 0.f; psp[i] = 0.f; }

    for (int kt = 0; kt < NKT; kt++) {
        const int k0 = kt * TK;

        // ======== QK phase: warp = head w, lane = k (d4-outer, low regs) ========
        {
            float sacc[8];
#pragma unroll
            for (int q = 0; q < 8; q++) sacc[q] = 0.f;
            const float* kp = ktb + k0 + lane;
#pragma unroll
            for (int d4 = 0; d4 < 8; d4++) {
                float k0r = kp[(size_t)(d4 * 4 + 0) * LSEQ];
                float k1r = kp[(size_t)(d4 * 4 + 1) * LSEQ];
                float k2r = kp[(size_t)(d4 * 4 + 2) * LSEQ];
                float k3r = kp[(size_t)(d4 * 4 + 3) * LSEQ];
#pragma unroll
                for (int q = 0; q < 8; q++) {
                    float4 qd = reinterpret_cast<const float4*>(&QS[(w * TQ + q) * 32])[d4];
                    sacc[q] += qd.x * k0r + qd.y * k1r + qd.z * k2r + qd.w * k3r;
                }
            }
#pragma unroll
            for (int q = 0; q < 8; q++)
                PT[q * PT_Q + lane * 9 + w] = sacc[q];
        }
        __syncthreads();   // (1) Sqk visible; also orders prior ACC-V P2 reads vs BIAS writes

        // struct tile for this kt was issued one phase-group ago; wait now.
        cp_async_wait_all();

        // ======== BIAS phase: warp = q-row w, lane = k (s4-outer, low regs) ====
        {
            const int midx = b * LSEQ + k0 + lane;
            const bool masked = mask_is_byte ? (km8[midx] != 0) : (km32[midx] != 0);

            const float* stq = ST + w * ST_ROW + lane * DS;   // lane's k row (linear)
            float bias[8];
#pragma unroll
            for (int h2 = 0; h2 < 8; h2++) bias[h2] = 0.f;
#pragma unroll
            for (int s4 = 0; s4 < 7; s4++) {
                float v0 = stq[s4 * 4 + 0];
                float v1 = stq[s4 * 4 + 1];
                float v2 = stq[s4 * 4 + 2];
                float v3 = stq[s4 * 4 + 3];
#pragma unroll
                for (int h2 = 0; h2 < 8; h2++) {
                    float4 ww = reinterpret_cast<const float4*>(&QW[(h2 * TQ + w) * 32])[s4];
                    bias[h2] += ww.x * v0 + ww.y * v1 + ww.z * v2 + ww.w * v3;
                }
            }
            {
                float v0 = stq[28], v1 = stq[29];
#pragma unroll
                for (int h2 = 0; h2 < 8; h2++)
                    bias[h2] += QW[(h2 * TQ + w) * 32 + 28] * v0
                              + QW[(h2 * TQ + w) * 32 + 29] * v1;
            }
            float pq0 = 0.f;
#pragma unroll
            for (int h2 = 0; h2 < 8; h2++) {
                float sc = PT[w * PT_Q + lane * 9 + h2] + bias[h2];
                float p = masked ? 0.f : __expf(sc);
                if (h2 == 0) pq0 = p;
                P2[(w * 8 + h2) * P2R + lane] = p;
            }
            scores0[((size_t)(b * LSEQ + q0 + w)) * LSEQ + k0 + lane] = pq0;
        }
        __syncthreads();   // (2) p visible; PT reads complete (safe for next QK)

        // ======== ACC-PS: warp = q-row w, lane = s (LAST reader of own ST row) ==
        if (lane < DS) {
            const float* stq2 = ST + w * ST_ROW + lane;
            const float* pbase = &P2[(w * 8) * P2R];
#pragma unroll 4
            for (int k = 0; k < TK; k++) {
                float svk = stq2[k * DS];
#pragma unroll
                for (int h2 = 0; h2 < NH; h2++)
                    psp[h2] += pbase[h2 * P2R + k] * svk;
            }
        }

        // issue cp.async for next tile NOW — own ST row is free (warp-local),
        // and ACC-V + next QK hide the latency.
        if (kt + 1 < NKT) {
            const float* src = st_qrow + (size_t)(k0 + TK) * DS;
#pragma unroll
            for (int c = lane; c < 240; c += 32)
                cp_async16(st_dst + c * 4, src + c * 4);
            cp_async_commit();
        }

        // ======== ACC-V: warp = head w, lane = (aq, aoct) ========
        {
            const float* vbase = vh + ((size_t)(b * LSEQ + k0)) * DM + w * DH + aoct * 8;
            const float* prow = &P2[(aq * 8 + w) * P2R];
#pragma unroll 4
            for (int k = 0; k < TK; k++) {
                float p = prow[k];
                float4 v0 = *reinterpret_cast<const float4*>(vbase + (size_t)k * DM);
                float4 v1 = *reinterpret_cast<const float4*>(vbase + (size_t)k * DM + 4);
                acc[0] += p * v0.x; acc[1] += p * v0.y; acc[2] += p * v0.z; acc[3] += p * v0.w;
                acc[4] += p * v1.x; acc[5] += p * v1.y; acc[6] += p * v1.z; acc[7] += p * v1.w;
                lsum += p;
            }
        }
        // no sync here: P2 reads (ACC-V) complete before sync(1) of next tile,
        // which precedes the next BIAS's P2 writes.
    }

    // ---- epilogue ----
    if (aoct == 0) LS[aq * 9 + w] = lsum;        // lsum for (h=w, q=aq)
    __syncthreads();                              // PT dead -> PS overlay safe
    if (lane < DS) {
#pragma unroll
        for (int h2 = 0; h2 < NH; h2++)
            PS[(w * 8 + h2) * P2R + lane] = psp[h2];   // ps for (q=w, h2, s=lane)
    }
    __syncthreads();

    // final: warp = head w, lane = (aq, aoct)
    {
        float linv = 1.f / LS[aq * 9 + w];
        float c[8];
#pragma unroll
        for (int j = 0; j < 8; j++) c[j] = acc[j];

        const float* psrow = &PS[(aq * 8 + w) * P2R];
#pragma unroll
        for (int s = 0; s < DS; s++) {
            float pv = psrow[s];
            const float* wr = &WSV[s * 33 + aoct * 8];
#pragma unroll
            for (int j = 0; j < 8; j++) c[j] += pv * wr[j];
        }
#pragma unroll
        for (int j = 0; j < 8; j++) c[j] = c[j] * linv + bsv[aoct * 8 + j];

        float* outp = &ctx[((size_t)(b * LSEQ + q0 + aq)) * DM + w * DH + aoct * 8];
        float4 o0 = { c[0], c[1], c[2], c[3] };
        float4 o1 = { c[4], c[5], c[6], c[7] };
        reinterpret_cast<float4*>(outp)[0] = o0;
        reinterpret_cast<float4*>(outp)[1] = o1;
    }
}

// ---------------------------------------------------------------------------
__global__ void __launch_bounds__(256) normalize_rows(
    const float* __restrict__ P, float* __restrict__ O)
{
    const int row = blockIdx.x;
    const float* s = P + (size_t)row * LSEQ;
    float* o = O + (size_t)row * LSEQ;
    const int t = threadIdx.x;

    float a = s[t], b = s[t + 256];
    float sum = a + b;
    __shared__ float red[8];
#pragma unroll
    for (int off = 16; off; off >>= 1) sum += __shfl_xor_sync(0xffffffffu, sum, off);
    if ((t & 31) == 0) red[t >> 5] = sum;
    __syncthreads();
    float sAll = 0.f;
#pragma unroll
    for (int i = 0; i < 8; i++) sAll += red[i];
    float inv = 1.f / sAll;
    o[t] = a * inv;
    o[t + 256] = b * inv;
}

// ---------------------------------------------------------------------------
extern "C" void kernel_launch(void* const* d_in, const int* in_sizes, int n_in,
                              void* d_out, int out_size)
{
    const float* key   = (const float*)d_in[0];
    const float* value = (const float*)d_in[1];
    const float* query = (const float*)d_in[2];

    const float* structure;
    const void*  kmaskp;
    if (in_sizes[3] == BSZ * LSEQ) {
        kmaskp    = d_in[3];
        structure = (const float*)d_in[4];
    } else {
        structure = (const float*)d_in[3];
        kmaskp    = d_in[4];
    }

    const float* wq  = (const float*)d_in[5];
    const float* bq  = (const float*)d_in[6];
    const float* wk  = (const float*)d_in[7];
    const float* bk  = (const float*)d_in[8];
    const float* wv  = (const float*)d_in[9];
    const float* bv  = (const float*)d_in[10];
    const float* wsk = (const float*)d_in[11];
    // d_in[12] = bsk: softmax-invariant, dropped.
    const float* wsv = (const float*)d_in[13];
    const float* bsv = (const float*)d_in[14];
    const float* wf  = (const float*)d_in[15];
    const float* bf  = (const float*)d_in[16];

    float* out = (float*)d_out;
    float* fin = out + (size_t)BSZ * LSEQ * DM;

    float* scratch = nullptr;
    cudaGetSymbolAddress((void**)&scratch, g_scratch);
    float* qh  = scratch;
    float* kh  = qh + (size_t)BSZ * LSEQ * DM;
    float* vh  = kh + (size_t)BSZ * LSEQ * DM;
    float* ctx = vh + (size_t)BSZ * LSEQ * DM;
    float* ktr = ctx + (size_t)BSZ * LSEQ * DM;
    float* sc0 = ktr + (size_t)BSZ * LSEQ * DM;

    detect_mask_kernel<<<1, 256>>>((const unsigned char*)kmaskp, BSZ * LSEQ);

    qkv_gemm<<<dim3(2, 32, 3), 256>>>(query, key, value,
                                      wq, wk, wv, bq, bk, bv,
                                      qh, kh, vh);

    transpose_k<<<dim3(16, 8, 8), dim3(32, 8)>>>(kh, ktr);

    cudaFuncSetAttribute(attn_kernel, cudaFuncAttributeMaxDynamicSharedMemorySize, SMEM_BYTES);
    attn_kernel<<<BSZ * (LSEQ / TQ), NTHREADS, SMEM_BYTES>>>(
        qh, ktr, vh, structure, kmaskp, wsk, wsv, bsv, ctx, sc0);

    normalize_rows<<<BSZ * LSEQ, 256>>>(sc0, fin);
    gemm128<<<dim3(2, 32), 256>>>(ctx, wf, bf, out, 1.0f);
}

// round 15
// speedup vs baseline: 1.1936x; 1.1465x over previous
#include <cuda_runtime.h>
#include <math.h>

#define BSZ 8
#define LSEQ 512
#define DM 256
#define NH 8
#define DH 32
#define DS 30

#define TQ 8       // q rows per CTA; warp w is head w AND q-row w (role switch)
#define TK 32
#define NKT (LSEQ / TK)
#define NTHREADS 256

#define ST_ROW 960            // linear [k*30+s] per q-row (warp-local)
#define PT_Q 289              // Sqk [q][k*9+h]
#define P2R 33                // p rows [(q*8+h)][33]

// ---- attn dynamic smem layout (float offsets), total 18230 fl = 72.9 KB ----
#define OFF_QS  0              // [8h][8q][32]  = 2048
#define OFF_QW  2048           // [8h][8q][32]  = 2048 (qwsk, s padded 30->32 zeros)
#define OFF_ST  4096           // 8q * 960      = 7680 (warp-local rows)
#define OFF_PT  11776          // 8 * 289       = 2312 (PS overlays this in epilogue)
#define OFF_P2  14088          // 64 * 33       = 2112
#define OFF_WSK 16200          // 960
#define OFF_WSV 17160          // 30*33 = 990
#define OFF_LS  18150          // 80
#define SMEM_FLOATS 18230
#define SMEM_BYTES (SMEM_FLOATS * 4)

// scratch: qh, kh, vh, ctx, ktr (1M fl each) + scores0 (2M fl)
__device__ float g_scratch[5 * BSZ * LSEQ * DM + BSZ * LSEQ * LSEQ];
__device__ int g_mask_is_byte;

// cp.async 16B helper
__device__ __forceinline__ void cp_async16(void* smem_dst, const void* gmem_src)
{
    unsigned saddr = (unsigned)__cvta_generic_to_shared(smem_dst);
    asm volatile("cp.async.cg.shared.global [%0], [%1], 16;" :: "r"(saddr), "l"(gmem_src));
}
__device__ __forceinline__ void cp_async_commit() { asm volatile("cp.async.commit_group;"); }
__device__ __forceinline__ void cp_async_wait_all() { asm volatile("cp.async.wait_group 0;"); }

// ---------------------------------------------------------------------------
__global__ void detect_mask_kernel(const unsigned char* __restrict__ m, int nbytes)
{
    __shared__ int any;
    if (threadIdx.x == 0) any = 0;
    __syncthreads();
    int local = 0;
    for (int i = threadIdx.x; i < nbytes; i += blockDim.x)
        if ((i & 3) != 0 && m[i] != 0) local = 1;
    if (local) atomicOr(&any, 1);
    __syncthreads();
    if (threadIdx.x == 0) g_mask_is_byte = any;
}

// ---------------------------------------------------------------------------
// K transpose: ktr[b][n][m] = kh[b*512+m][n]
// ---------------------------------------------------------------------------
__global__ void __launch_bounds__(256) transpose_k(
    const float* __restrict__ kh, float* __restrict__ ktr)
{
    __shared__ float t[32][33];
    const int b = blockIdx.z;
    const int m0 = blockIdx.x * 32, n0 = blockIdx.y * 32;
    const int tx = threadIdx.x, ty = threadIdx.y;

    for (int r = ty; r < 32; r += 8)
        t[r][tx] = kh[(size_t)(b * LSEQ + m0 + r) * DM + n0 + tx];
    __syncthreads();
    for (int r = ty; r < 32; r += 8)
        ktr[(size_t)b * DM * LSEQ + (size_t)(n0 + r) * LSEQ + m0 + tx] = t[tx][r];
}

// ---------------------------------------------------------------------------
// SGEMM 128x128 tile, 256 threads, 8x8 microtile, double-buffered.
// ---------------------------------------------------------------------------
__device__ __forceinline__ void gemm128_body(
    const float* __restrict__ A, const float* __restrict__ W,
    const float* __restrict__ bias, float* __restrict__ C, float scale,
    int m0, int n0)
{
    __shared__ float As[2][8][128];
    __shared__ float Bs[2][8][128];

    const int tid = threadIdx.x;
    const int am = tid >> 1;
    const int ak = (tid & 1) * 4;
    const int br = tid >> 5;
    const int bc = (tid & 31) * 4;
    const int tx = tid & 15, ty = tid >> 4;

    float4 av = *reinterpret_cast<const float4*>(&A[(size_t)(m0 + am) * 256 + ak]);
    float4 bv = *reinterpret_cast<const float4*>(&W[(size_t)br * 256 + n0 + bc]);

    As[0][ak + 0][am] = av.x; As[0][ak + 1][am] = av.y;
    As[0][ak + 2][am] = av.z; As[0][ak + 3][am] = av.w;
    *reinterpret_cast<float4*>(&Bs[0][br][bc]) = bv;
    __syncthreads();

    float acc[8][8] = {};
    int buf = 0;

    for (int k0 = 0; k0 < 256; k0 += 8) {
        const bool more = (k0 + 8 < 256);
        if (more) {
            av = *reinterpret_cast<const float4*>(&A[(size_t)(m0 + am) * 256 + k0 + 8 + ak]);
            bv = *reinterpret_cast<const float4*>(&W[(size_t)(k0 + 8 + br) * 256 + n0 + bc]);
        }
#pragma unroll
        for (int kk = 0; kk < 8; kk++) {
            float a[8], b[8];
            *reinterpret_cast<float4*>(&a[0]) = *reinterpret_cast<const float4*>(&As[buf][kk][ty * 8]);
            *reinterpret_cast<float4*>(&a[4]) = *reinterpret_cast<const float4*>(&As[buf][kk][ty * 8 + 4]);
            *reinterpret_cast<float4*>(&b[0]) = *reinterpret_cast<const float4*>(&Bs[buf][kk][tx * 8]);
            *reinterpret_cast<float4*>(&b[4]) = *reinterpret_cast<const float4*>(&Bs[buf][kk][tx * 8 + 4]);
#pragma unroll
            for (int i = 0; i < 8; i++)
#pragma unroll
                for (int j = 0; j < 8; j++) acc[i][j] += a[i] * b[j];
        }
        if (more) {
            buf ^= 1;
            As[buf][ak + 0][am] = av.x; As[buf][ak + 1][am] = av.y;
            As[buf][ak + 2][am] = av.z; As[buf][ak + 3][am] = av.w;
            *reinterpret_cast<float4*>(&Bs[buf][br][bc]) = bv;
            __syncthreads();
        }
    }

    float bb[8];
#pragma unroll
    for (int j = 0; j < 8; j++) bb[j] = bias[n0 + tx * 8 + j];
#pragma unroll
    for (int i = 0; i < 8; i++) {
        float4 c0, c1;
        c0.x = (acc[i][0] + bb[0]) * scale; c0.y = (acc[i][1] + bb[1]) * scale;
        c0.z = (acc[i][2] + bb[2]) * scale; c0.w = (acc[i][3] + bb[3]) * scale;
        c1.x = (acc[i][4] + bb[4]) * scale; c1.y = (acc[i][5] + bb[5]) * scale;
        c1.z = (acc[i][6] + bb[6]) * scale; c1.w = (acc[i][7] + bb[7]) * scale;
        float* cp = &C[(size_t)(m0 + ty * 8 + i) * 256 + n0 + tx * 8];
        reinterpret_cast<float4*>(cp)[0] = c0;
        reinterpret_cast<float4*>(cp)[1] = c1;
    }
}

__global__ void __launch_bounds__(256) gemm128(
    const float* __restrict__ A, const float* __restrict__ W,
    const float* __restrict__ bias, float* __restrict__ C, float scale)
{
    gemm128_body(A, W, bias, C, scale, blockIdx.y * 128, blockIdx.x * 128);
}

__global__ void __launch_bounds__(256) qkv_gemm(
    const float* __restrict__ Aq, const float* __restrict__ Ak, const float* __restrict__ Av,
    const float* __restrict__ Wq, const float* __restrict__ Wk, const float* __restrict__ Wv,
    const float* __restrict__ bq, const float* __restrict__ bk, const float* __restrict__ bv,
    float* __restrict__ Cq, float* __restrict__ Ck, float* __restrict__ Cv)
{
    const float *A, *W, *bias; float* C; float scale;
    if (blockIdx.z == 0)      { A = Aq; W = Wq; bias = bq; C = Cq; scale = 0.17677669529663688f; }
    else if (blockIdx.z == 1) { A = Ak; W = Wk; bias = bk; C = Ck; scale = 1.0f; }
    else                      { A = Av; W = Wv; bias = bv; C = Cv; scale = 1.0f; }
    gemm128_body(A, W, bias, C, scale, blockIdx.y * 128, blockIdx.x * 128);
}

// ---------------------------------------------------------------------------
// Fused attention, fixed-max softmax, role-switching warps, 3 CTAs/SM.
// cp.async ST staging (warp-local rows, issued after ACC-PS, waited after QK).
// QK/BIAS restructured for high MLP at moderate register count:
//   QK: kreg[16] halves (16 LDGs in flight), BIAS: float2 sv batches.
// ---------------------------------------------------------------------------
__global__ void __launch_bounds__(NTHREADS, 3) attn_kernel(
    const float* __restrict__ qh, const float* __restrict__ ktr, const float* __restrict__ vh,
    const float* __restrict__ st_g, const void* __restrict__ kmask_raw,
    const float* __restrict__ wsk, const float* __restrict__ wsv, const float* __restrict__ bsv,
    float* __restrict__ ctx, float* __restrict__ scores0)
{
    extern __shared__ float sm[];
    float* QS  = sm + OFF_QS;
    float* QW  = sm + OFF_QW;
    float* ST  = sm + OFF_ST;
    float* PT  = sm + OFF_PT;
    float* P2  = sm + OFF_P2;
    float* WSK = sm + OFF_WSK;
    float* WSV = sm + OFF_WSV;
    float* LS  = sm + OFF_LS;
    float* PS  = sm + OFF_PT;   // overlays PT (dead after last BIAS)

    const int tid = threadIdx.x;
    const int w = tid >> 5, lane = tid & 31;
    const int aq = lane >> 2, aoct = lane & 3;    // ACC-V / epilogue lane identity
    const int b = blockIdx.x >> 6;
    const int q0 = (blockIdx.x & 63) * TQ;
    const int mask_is_byte = g_mask_is_byte;
    const unsigned char* km8 = (const unsigned char*)kmask_raw;
    const int* km32 = (const int*)kmask_raw;

    // struct staging: warp w stages q-row w, linear layout, cp.async (warp-local!)
    const float* st_qrow = st_g + (((size_t)b * LSEQ + q0 + w) * LSEQ) * DS;
    float* st_dst = ST + w * ST_ROW;

    const float* ktb = ktr + (size_t)b * DM * LSEQ + (size_t)(w * DH) * LSEQ;

    // ---- issue cp.async for tile 0 immediately (waited before first BIAS) ----
    {
        const float* src = st_qrow;
#pragma unroll
        for (int c = lane; c < 240; c += 32)
            cp_async16(st_dst + c * 4, src + c * 4);
        cp_async_commit();
    }

    // ---- init: QS, WSK, WSV, zero QW ----
    {
        const float4* qg4 = reinterpret_cast<const float4*>(qh + ((size_t)b * LSEQ + q0) * DM);
        for (int f = tid; f < TQ * DM / 4; f += NTHREADS) {
            int q = f >> 6, c4 = f & 63;
            float4 v = qg4[f];
            int hh = c4 >> 3, d = (c4 & 7) * 4;
            float* dst = &QS[(hh * TQ + q) * 32 + d];
            dst[0] = v.x; dst[1] = v.y; dst[2] = v.z; dst[3] = v.w;
        }
    }
    for (int i = tid; i < DS * DH; i += NTHREADS) WSK[i] = wsk[i];
    for (int i = tid; i < DS * DH; i += NTHREADS) {
        int s = i >> 5, d = i & 31;
        WSV[s * 33 + d] = wsv[i];
    }
    for (int i = tid; i < NH * TQ * 32; i += NTHREADS) QW[i] = 0.f;
    __syncthreads();

    // qwsk[h,q,s] = sum_d QS[h,q,d] * wsk[s,d]
    for (int i = tid; i < NH * TQ * DS; i += NTHREADS) {
        int hh = i / (TQ * DS);
        int r = i - hh * (TQ * DS);
        int q = r / DS;
        int s = r - q * DS;
        const float* qp = &QS[(hh * TQ + q) * 32];
        const float* wp = &WSK[s * 32];
        float a = 0.f;
#pragma unroll
        for (int d = 0; d < 32; d++) a += qp[d] * wp[d];
        QW[(hh * TQ + q) * 32 + s] = a;
    }
    __syncthreads();          // QW visible to all

    float acc[8], psp[8];
    float lsum = 0.f;
#pragma unroll
    for (int i = 0; i < 8; i++) { acc[i] = 0.f; psp[i] = 0.f; }

    for (int kt = 0; kt < NKT; kt++) {
        const int k0 = kt * TK;

        // ======== QK phase: warp = head w, lane = k (kreg halves, MLP=16) =====
        {
            float sacc[8];
#pragma unroll
            for (int q = 0; q < 8; q++) sacc[q] = 0.f;
            const float* kp = ktb + k0 + lane;
#pragma unroll
            for (int half = 0; half < 2; half++) {
                float kreg[16];
#pragma unroll
                for (int d = 0; d < 16; d++)
                    kreg[d] = kp[(size_t)(half * 16 + d) * LSEQ];
#pragma unroll
                for (int q = 0; q < 8; q++) {
                    const float4* qv = reinterpret_cast<const float4*>(
                        &QS[(w * TQ + q) * 32 + half * 16]);
#pragma unroll
                    for (int d4 = 0; d4 < 4; d4++) {
                        float4 qd = qv[d4];
                        sacc[q] += qd.x * kreg[d4 * 4] + qd.y * kreg[d4 * 4 + 1]
                                 + qd.z * kreg[d4 * 4 + 2] + qd.w * kreg[d4 * 4 + 3];
                    }
                }
            }
#pragma unroll
            for (int q = 0; q < 8; q++)
                PT[q * PT_Q + lane * 9 + w] = sacc[q];
        }
        __syncthreads();   // (1) Sqk visible; orders prior ACC-V P2 reads vs BIAS writes

        // struct tile for this kt was issued one phase-group ago; wait now.
        cp_async_wait_all();

        // ======== BIAS phase: warp = q-row w, lane = k (float2 sv batches) ====
        {
            const int midx = b * LSEQ + k0 + lane;
            const bool masked = mask_is_byte ? (km8[midx] != 0) : (km32[midx] != 0);

            const float2* stq2v = reinterpret_cast<const float2*>(ST + w * ST_ROW + lane * DS);
            float bias[8];
#pragma unroll
            for (int h2 = 0; h2 < 8; h2++) bias[h2] = 0.f;

            {   // batch 0: s = 0..15 (8 float2 LDS in flight)
                float sv[16];
#pragma unroll
                for (int i = 0; i < 8; i++) {
                    float2 t = stq2v[i];
                    sv[2 * i] = t.x; sv[2 * i + 1] = t.y;
                }
#pragma unroll
                for (int h2 = 0; h2 < 8; h2++) {
                    const float4* qw4 = reinterpret_cast<const float4*>(&QW[(h2 * TQ + w) * 32]);
#pragma unroll
                    for (int s4 = 0; s4 < 4; s4++) {
                        float4 ww = qw4[s4];
                        bias[h2] += ww.x * sv[s4 * 4] + ww.y * sv[s4 * 4 + 1]
                                  + ww.z * sv[s4 * 4 + 2] + ww.w * sv[s4 * 4 + 3];
                    }
                }
            }
            {   // batch 1: s = 16..29 (7 float2 LDS in flight)
                float sv[14];
#pragma unroll
                for (int i = 0; i < 7; i++) {
                    float2 t = stq2v[8 + i];
                    sv[2 * i] = t.x; sv[2 * i + 1] = t.y;
                }
#pragma unroll
                for (int h2 = 0; h2 < 8; h2++) {
                    const float4* qw4 = reinterpret_cast<const float4*>(&QW[(h2 * TQ + w) * 32 + 16]);
#pragma unroll
                    for (int s4 = 0; s4 < 3; s4++) {
                        float4 ww = qw4[s4];
                        bias[h2] += ww.x * sv[s4 * 4] + ww.y * sv[s4 * 4 + 1]
                                  + ww.z * sv[s4 * 4 + 2] + ww.w * sv[s4 * 4 + 3];
                    }
                    bias[h2] += QW[(h2 * TQ + w) * 32 + 28] * sv[12]
                              + QW[(h2 * TQ + w) * 32 + 29] * sv[13];
                }
            }

            float pq0 = 0.f;
#pragma unroll
            for (int h2 = 0; h2 < 8; h2++) {
                float sc = PT[w * PT_Q + lane * 9 + h2] + bias[h2];
                float p = masked ? 0.f : __expf(sc);
                if (h2 == 0) pq0 = p;
                P2[(w * 8 + h2) * P2R + lane] = p;
            }
            scores0[((size_t)(b * LSEQ + q0 + w)) * LSEQ + k0 + lane] = pq0;
        }
        __syncthreads();   // (2) p visible; PT reads complete (safe for next QK)

        // ======== ACC-PS: warp = q-row w, lane = s (LAST reader of own ST row) ==
        if (lane < DS) {
            const float* stq2 = ST + w * ST_ROW + lane;
            const float* pbase = &P2[(w * 8) * P2R];
#pragma unroll 4
            for (int k = 0; k < TK; k++) {
                float svk = stq2[k * DS];
#pragma unroll
                for (int h2 = 0; h2 < NH; h2++)
                    psp[h2] += pbase[h2 * P2R + k] * svk;
            }
        }

        // issue cp.async for next tile NOW — own ST row is free (warp-local),
        // ACC-V + next QK hide the latency.
        if (kt + 1 < NKT) {
            const float* src = st_qrow + (size_t)(k0 + TK) * DS;
#pragma unroll
            for (int c = lane; c < 240; c += 32)
                cp_async16(st_dst + c * 4, src + c * 4);
            cp_async_commit();
        }

        // ======== ACC-V: warp = head w, lane = (aq, aoct) ========
        {
            const float* vbase = vh + ((size_t)(b * LSEQ + k0)) * DM + w * DH + aoct * 8;
            const float* prow = &P2[(aq * 8 + w) * P2R];
#pragma unroll 4
            for (int k = 0; k < TK; k++) {
                float p = prow[k];
                float4 v0 = *reinterpret_cast<const float4*>(vbase + (size_t)k * DM);
                float4 v1 = *reinterpret_cast<const float4*>(vbase + (size_t)k * DM + 4);
                acc[0] += p * v0.x; acc[1] += p * v0.y; acc[2] += p * v0.z; acc[3] += p * v0.w;
                acc[4] += p * v1.x; acc[5] += p * v1.y; acc[6] += p * v1.z; acc[7] += p * v1.w;
                lsum += p;
            }
        }
        // no sync: ACC-V P2 reads complete before next tile's sync (1),
        // which precedes the next BIAS's P2 writes.
    }

    // ---- epilogue ----
    if (aoct == 0) LS[aq * 9 + w] = lsum;        // lsum for (h=w, q=aq)
    __syncthreads();                              // PT dead -> PS overlay safe
    if (lane < DS) {
#pragma unroll
        for (int h2 = 0; h2 < NH; h2++)
            PS[(w * 8 + h2) * P2R + lane] = psp[h2];   // ps for (q=w, h2, s=lane)
    }
    __syncthreads();

    // final: warp = head w, lane = (aq, aoct)
    {
        float linv = 1.f / LS[aq * 9 + w];
        float c[8];
#pragma unroll
        for (int j = 0; j < 8; j++) c[j] = acc[j];

        const float* psrow = &PS[(aq * 8 + w) * P2R];
#pragma unroll
        for (int s = 0; s < DS; s++) {
            float pv = psrow[s];
            const float* wr = &WSV[s * 33 + aoct * 8];
#pragma unroll
            for (int j = 0; j < 8; j++) c[j] += pv * wr[j];
        }
#pragma unroll
        for (int j = 0; j < 8; j++) c[j] = c[j] * linv + bsv[aoct * 8 + j];

        float* outp = &ctx[((size_t)(b * LSEQ + q0 + aq)) * DM + w * DH + aoct * 8];
        float4 o0 = { c[0], c[1], c[2], c[3] };
        float4 o1 = { c[4], c[5], c[6], c[7] };
        reinterpret_cast<float4*>(outp)[0] = o0;
        reinterpret_cast<float4*>(outp)[1] = o1;
    }
}

// ---------------------------------------------------------------------------
__global__ void __launch_bounds__(256) normalize_rows(
    const float* __restrict__ P, float* __restrict__ O)
{
    const int row = blockIdx.x;
    const float* s = P + (size_t)row * LSEQ;
    float* o = O + (size_t)row * LSEQ;
    const int t = threadIdx.x;

    float a = s[t], b = s[t + 256];
    float sum = a + b;
    __shared__ float red[8];
#pragma unroll
    for (int off = 16; off; off >>= 1) sum += __shfl_xor_sync(0xffffffffu, sum, off);
    if ((t & 31) == 0) red[t >> 5] = sum;
    __syncthreads();
    float sAll = 0.f;
#pragma unroll
    for (int i = 0; i < 8; i++) sAll += red[i];
    float inv = 1.f / sAll;
    o[t] = a * inv;
    o[t + 256] = b * inv;
}

// ---------------------------------------------------------------------------
extern "C" void kernel_launch(void* const* d_in, const int* in_sizes, int n_in,
                              void* d_out, int out_size)
{
    const float* key   = (const float*)d_in[0];
    const float* value = (const float*)d_in[1];
    const float* query = (const float*)d_in[2];

    const float* structure;
    const void*  kmaskp;
    if (in_sizes[3] == BSZ * LSEQ) {
        kmaskp    = d_in[3];
        structure = (const float*)d_in[4];
    } else {
        structure = (const float*)d_in[3];
        kmaskp    = d_in[4];
    }

    const float* wq  = (const float*)d_in[5];
    const float* bq  = (const float*)d_in[6];
    const float* wk  = (const float*)d_in[7];
    const float* bk  = (const float*)d_in[8];
    const float* wv  = (const float*)d_in[9];
    const float* bv  = (const float*)d_in[10];
    const float* wsk = (const float*)d_in[11];
    // d_in[12] = bsk: softmax-invariant, dropped.
    const float* wsv = (const float*)d_in[13];
    const float* bsv = (const float*)d_in[14];
    const float* wf  = (const float*)d_in[15];
    const float* bf  = (const float*)d_in[16];

    float* out = (float*)d_out;
    float* fin = out + (size_t)BSZ * LSEQ * DM;

    float* scratch = nullptr;
    cudaGetSymbolAddress((void**)&scratch, g_scratch);
    float* qh  = scratch;
    float* kh  = qh + (size_t)BSZ * LSEQ * DM;
    float* vh  = kh + (size_t)BSZ * LSEQ * DM;
    float* ctx = vh + (size_t)BSZ * LSEQ * DM;
    float* ktr = ctx + (size_t)BSZ * LSEQ * DM;
    float* sc0 = ktr + (size_t)BSZ * LSEQ * DM;

    detect_mask_kernel<<<1, 256>>>((const unsigned char*)kmaskp, BSZ * LSEQ);

    qkv_gemm<<<dim3(2, 32, 3), 256>>>(query, key, value,
                                      wq, wk, wv, bq, bk, bv,
                                      qh, kh, vh);

    transpose_k<<<dim3(16, 8, 8), dim3(32, 8)>>>(kh, ktr);

    cudaFuncSetAttribute(attn_kernel, cudaFuncAttributeMaxDynamicSharedMemorySize, SMEM_BYTES);
    attn_kernel<<<BSZ * (LSEQ / TQ), NTHREADS, SMEM_BYTES>>>(
        qh, ktr, vh, structure, kmaskp, wsk, wsv, bsv, ctx, sc0);

    normalize_rows<<<BSZ * LSEQ, 256>>>(sc0, fin);
    gemm128<<<dim3(2, 32), 256>>>(ctx, wf, bf, out, 1.0f);
}

// round 16
// speedup vs baseline: 1.3142x; 1.1011x over previous
#include <cuda_runtime.h>
#include <math.h>

#define BSZ 8
#define LSEQ 512
#define DM 256
#define NH 8
#define DH 32
#define DS 30

#define TQ 8       // q rows per CTA; warp w is head w AND q-row w (role switch)
#define TK 32
#define NKT (LSEQ / TK)
#define NTHREADS 256

#define ST_K 31               // [k][s] stride (banks s-k, conflict-free)
#define ST_Q (32 * ST_K)      // 992 per q-row (warp-local)
#define PT_Q 289              // Sqk [q][k*9+h]
#define P2R 33                // p rows [(q*8+h)][33]

// ---- attn dynamic smem layout (float offsets), 20608 fl = 82.4 KB ----
#define OFF_QS  0              // [8h][8q][32]  = 2048
#define OFF_QW  2048           // [8h][8q][32]  = 2048 (qwsk, s padded 30->32 zeros)
#define OFF_ST  4096           // 8q * 992      = 7936
#define OFF_PT  12032          // 8 * 289       = 2312
#define OFF_P2  14344          // 64 * 33       = 2112
#define OFF_PS  16456          // 64 * 33       = 2112 (epilogue ps)
#define OFF_WSK 18568          // 960
#define OFF_WSV 19528          // 30*33 = 990
#define OFF_LS  20518          // 80
#define SMEM_FLOATS 20608
#define SMEM_BYTES (SMEM_FLOATS * 4)

// scratch: qh, kh, vh, ctx, ktr (1M fl each) + scores0 (2M fl)
__device__ float g_scratch[5 * BSZ * LSEQ * DM + BSZ * LSEQ * LSEQ];
__device__ int g_mask_is_byte;

// ---------------------------------------------------------------------------
__global__ void detect_mask_kernel(const unsigned char* __restrict__ m, int nbytes)
{
    __shared__ int any;
    if (threadIdx.x == 0) any = 0;
    __syncthreads();
    int local = 0;
    for (int i = threadIdx.x; i < nbytes; i += blockDim.x)
        if ((i & 3) != 0 && m[i] != 0) local = 1;
    if (local) atomicOr(&any, 1);
    __syncthreads();
    if (threadIdx.x == 0) g_mask_is_byte = any;
}

// ---------------------------------------------------------------------------
// K transpose: ktr[b][n][m] = kh[b*512+m][n]
// ---------------------------------------------------------------------------
__global__ void __launch_bounds__(256) transpose_k(
    const float* __restrict__ kh, float* __restrict__ ktr)
{
    __shared__ float t[32][33];
    const int b = blockIdx.z;
    const int m0 = blockIdx.x * 32, n0 = blockIdx.y * 32;
    const int tx = threadIdx.x, ty = threadIdx.y;

    for (int r = ty; r < 32; r += 8)
        t[r][tx] = kh[(size_t)(b * LSEQ + m0 + r) * DM + n0 + tx];
    __syncthreads();
    for (int r = ty; r < 32; r += 8)
        ktr[(size_t)b * DM * LSEQ + (size_t)(n0 + r) * LSEQ + m0 + tx] = t[tx][r];
}

// ---------------------------------------------------------------------------
// SGEMM 128x128 tile, 256 threads, 8x8 microtile, double-buffered.
// ---------------------------------------------------------------------------
__device__ __forceinline__ void gemm128_body(
    const float* __restrict__ A, const float* __restrict__ W,
    const float* __restrict__ bias, float* __restrict__ C, float scale,
    int m0, int n0)
{
    __shared__ float As[2][8][128];
    __shared__ float Bs[2][8][128];

    const int tid = threadIdx.x;
    const int am = tid >> 1;
    const int ak = (tid & 1) * 4;
    const int br = tid >> 5;
    const int bc = (tid & 31) * 4;
    const int tx = tid & 15, ty = tid >> 4;

    float4 av = *reinterpret_cast<const float4*>(&A[(size_t)(m0 + am) * 256 + ak]);
    float4 bv = *reinterpret_cast<const float4*>(&W[(size_t)br * 256 + n0 + bc]);

    As[0][ak + 0][am] = av.x; As[0][ak + 1][am] = av.y;
    As[0][ak + 2][am] = av.z; As[0][ak + 3][am] = av.w;
    *reinterpret_cast<float4*>(&Bs[0][br][bc]) = bv;
    __syncthreads();

    float acc[8][8] = {};
    int buf = 0;

    for (int k0 = 0; k0 < 256; k0 += 8) {
        const bool more = (k0 + 8 < 256);
        if (more) {
            av = *reinterpret_cast<const float4*>(&A[(size_t)(m0 + am) * 256 + k0 + 8 + ak]);
            bv = *reinterpret_cast<const float4*>(&W[(size_t)(k0 + 8 + br) * 256 + n0 + bc]);
        }
#pragma unroll
        for (int kk = 0; kk < 8; kk++) {
            float a[8], b[8];
            *reinterpret_cast<float4*>(&a[0]) = *reinterpret_cast<const float4*>(&As[buf][kk][ty * 8]);
            *reinterpret_cast<float4*>(&a[4]) = *reinterpret_cast<const float4*>(&As[buf][kk][ty * 8 + 4]);
            *reinterpret_cast<float4*>(&b[0]) = *reinterpret_cast<const float4*>(&Bs[buf][kk][tx * 8]);
            *reinterpret_cast<float4*>(&b[4]) = *reinterpret_cast<const float4*>(&Bs[buf][kk][tx * 8 + 4]);
#pragma unroll
            for (int i = 0; i < 8; i++)
#pragma unroll
                for (int j = 0; j < 8; j++) acc[i][j] += a[i] * b[j];
        }
        if (more) {
            buf ^= 1;
            As[buf][ak + 0][am] = av.x; As[buf][ak + 1][am] = av.y;
            As[buf][ak + 2][am] = av.z; As[buf][ak + 3][am] = av.w;
            *reinterpret_cast<float4*>(&Bs[buf][br][bc]) = bv;
            __syncthreads();
        }
    }

    float bb[8];
#pragma unroll
    for (int j = 0; j < 8; j++) bb[j] = bias[n0 + tx * 8 + j];
#pragma unroll
    for (int i = 0; i < 8; i++) {
        float4 c0, c1;
        c0.x = (acc[i][0] + bb[0]) * scale; c0.y = (acc[i][1] + bb[1]) * scale;
        c0.z = (acc[i][2] + bb[2]) * scale; c0.w = (acc[i][3] + bb[3]) * scale;
        c1.x = (acc[i][4] + bb[4]) * scale; c1.y = (acc[i][5] + bb[5]) * scale;
        c1.z = (acc[i][6] + bb[6]) * scale; c1.w = (acc[i][7] + bb[7]) * scale;
        float* cp = &C[(size_t)(m0 + ty * 8 + i) * 256 + n0 + tx * 8];
        reinterpret_cast<float4*>(cp)[0] = c0;
        reinterpret_cast<float4*>(cp)[1] = c1;
    }
}

__global__ void __launch_bounds__(256) gemm128(
    const float* __restrict__ A, const float* __restrict__ W,
    const float* __restrict__ bias, float* __restrict__ C, float scale)
{
    gemm128_body(A, W, bias, C, scale, blockIdx.y * 128, blockIdx.x * 128);
}

__global__ void __launch_bounds__(256) qkv_gemm(
    const float* __restrict__ Aq, const float* __restrict__ Ak, const float* __restrict__ Av,
    const float* __restrict__ Wq, const float* __restrict__ Wk, const float* __restrict__ Wv,
    const float* __restrict__ bq, const float* __restrict__ bk, const float* __restrict__ bv,
    float* __restrict__ Cq, float* __restrict__ Ck, float* __restrict__ Cv)
{
    const float *A, *W, *bias; float* C; float scale;
    if (blockIdx.z == 0)      { A = Aq; W = Wq; bias = bq; C = Cq; scale = 0.17677669529663688f; }
    else if (blockIdx.z == 1) { A = Ak; W = Wk; bias = bk; C = Ck; scale = 1.0f; }
    else                      { A = Av; W = Wv; bias = bv; C = Cv; scale = 1.0f; }
    gemm128_body(A, W, bias, C, scale, blockIdx.y * 128, blockIdx.x * 128);
}

// ---------------------------------------------------------------------------
// Fused attention, fixed-max softmax, role-switching warps, 2 CTAs/SM,
// register prefetch (MLP=15), TWO barriers per tile:
//   QK    (warp=head w, lane=k): Sqk -> PT          | sync(1)
//   BIAS  (warp=q-row w, lane=k): bias all 8 h -> P2 | sync(2)
//   ACC-V (warp=h=w, lane=(q,oct)): acc += p*V (LDG)
//   ACC-PS(warp=q=w, lane=s): ps += p*struct
//   commit prefetched ST (warp-local row -> NO barrier needed)
// Cross-warp safety: P2 reads (ACC-V) precede next sync(1) which precedes
// next BIAS P2 writes; PT reads (BIAS) precede sync(2) which precedes next
// QK PT writes.
// ---------------------------------------------------------------------------
__global__ void __launch_bounds__(NTHREADS, 2) attn_kernel(
    const float* __restrict__ qh, const float* __restrict__ ktr, const float* __restrict__ vh,
    const float* __restrict__ st_g, const void* __restrict__ kmask_raw,
    const float* __restrict__ wsk, const float* __restrict__ wsv, const float* __restrict__ bsv,
    float* __restrict__ ctx, float* __restrict__ scores0)
{
    extern __shared__ float sm[];
    float* QS  = sm + OFF_QS;
    float* QW  = sm + OFF_QW;
    float* ST  = sm + OFF_ST;
    float* PT  = sm + OFF_PT;
    float* P2  = sm + OFF_P2;
    float* PS  = sm + OFF_PS;
    float* WSK = sm + OFF_WSK;
    float* WSV = sm + OFF_WSV;
    float* LS  = sm + OFF_LS;

    const int tid = threadIdx.x;
    const int w = tid >> 5, lane = tid & 31;
    const int aq = lane >> 2, aoct = lane & 3;    // ACC-V lane identity
    const int b = blockIdx.x >> 6;
    const int q0 = (blockIdx.x & 63) * TQ;
    const int mask_is_byte = g_mask_is_byte;
    const unsigned char* km8 = (const unsigned char*)kmask_raw;
    const int* km32 = (const int*)kmask_raw;

    // struct staging: warp w stages q-row w (coalesced LDG + (k,s) walk scatter)
    const float* st_qrow = st_g + (((size_t)b * LSEQ + q0 + w) * LSEQ) * DS;
    float* st_dst = ST + w * ST_Q;
    const int ek0 = (lane * 2) / DS;
    const int es0 = (lane * 2) % DS;

    const float* ktb = ktr + (size_t)b * DM * LSEQ + (size_t)(w * DH) * LSEQ;

    // ---- init: QS, WSK, WSV, zero QW ----
    {
        const float4* qg4 = reinterpret_cast<const float4*>(qh + ((size_t)b * LSEQ + q0) * DM);
        for (int f = tid; f < TQ * DM / 4; f += NTHREADS) {
            int q = f >> 6, c4 = f & 63;
            float4 v = qg4[f];
            int hh = c4 >> 3, d = (c4 & 7) * 4;
            float* dst = &QS[(hh * TQ + q) * 32 + d];
            dst[0] = v.x; dst[1] = v.y; dst[2] = v.z; dst[3] = v.w;
        }
    }
    for (int i = tid; i < DS * DH; i += NTHREADS) WSK[i] = wsk[i];
    for (int i = tid; i < DS * DH; i += NTHREADS) {
        int s = i >> 5, d = i & 31;
        WSV[s * 33 + d] = wsv[i];
    }
    for (int i = tid; i < NH * TQ * 32; i += NTHREADS) QW[i] = 0.f;
    __syncthreads();

    // qwsk[h,q,s] = sum_d QS[h,q,d] * wsk[s,d]
    for (int i = tid; i < NH * TQ * DS; i += NTHREADS) {
        int hh = i / (TQ * DS);
        int r = i - hh * (TQ * DS);
        int q = r / DS;
        int s = r - q * DS;
        const float* qp = &QS[(hh * TQ + q) * 32];
        const float* wp = &WSK[s * 32];
        float a = 0.f;
#pragma unroll
        for (int d = 0; d < 32; d++) a += qp[d] * wp[d];
        QW[(hh * TQ + q) * 32 + s] = a;
    }

    // ---- initial ST staging for tile 0 (coalesced LDG, (k,s)-walk STS) ----
    float2 pre[15];
    {
        const float2* src = reinterpret_cast<const float2*>(st_qrow);
#pragma unroll
        for (int i = 0; i < 15; i++) pre[i] = src[i * 32 + lane];
    }
    {
        int kk = ek0, ss = es0;
#pragma unroll
        for (int i = 0; i < 15; i++) {
            st_dst[kk * ST_K + ss] = pre[i].x;
            int k2 = kk, s2 = ss + 1;
            if (s2 == DS) { s2 = 0; k2++; }
            st_dst[k2 * ST_K + s2] = pre[i].y;
            ss += 4; kk += 2;                 // e advances by 64 (= 2*30 + 4)
            if (ss >= DS) { ss -= DS; kk++; }
        }
    }
    __syncthreads();   // QW + (own) ST(0) ready

    float acc[8], psp[8];
    float lsum = 0.f;
#pragma unroll
    for (int i = 0; i < 8; i++) { acc[i] = 0.f; psp[i] = 0.f; }

    for (int kt = 0; kt < NKT; kt++) {
        const int k0 = kt * TK;

        // ======== QK phase: warp = head w, lane = k (kreg[32], MLP=32) ========
        {
            float kreg[32];
            const float* kp = ktb + k0 + lane;
#pragma unroll
            for (int d = 0; d < 32; d++) kreg[d] = kp[(size_t)d * LSEQ];

#pragma unroll
            for (int q = 0; q < TQ; q++) {
                const float4* qv = reinterpret_cast<const float4*>(&QS[(w * TQ + q) * 32]);
                float s = 0.f;
#pragma unroll
                for (int d4 = 0; d4 < 8; d4++) {
                    float4 qd = qv[d4];
                    s += qd.x * kreg[d4 * 4] + qd.y * kreg[d4 * 4 + 1]
                       + qd.z * kreg[d4 * 4 + 2] + qd.w * kreg[d4 * 4 + 3];
                }
                PT[q * PT_Q + lane * 9 + w] = s;
            }
        }
        __syncthreads();   // (1) Sqk visible; also orders prior ACC-V P2 reads vs BIAS writes

        // ======== BIAS phase: warp = q-row w, lane = k ========
        {
            const int midx = b * LSEQ + k0 + lane;
            const bool masked = mask_is_byte ? (km8[midx] != 0) : (km32[midx] != 0);

            float sv[32];
            const float* stq = ST + w * ST_Q + lane * ST_K;
#pragma unroll
            for (int s = 0; s < DS; s++) sv[s] = stq[s];
            sv[30] = 0.f; sv[31] = 0.f;

            float pq0 = 0.f;
#pragma unroll
            for (int h2 = 0; h2 < NH; h2++) {
                const float4* qw4 = reinterpret_cast<const float4*>(&QW[(h2 * TQ + w) * 32]);
                float bias = 0.f;
#pragma unroll
                for (int s4 = 0; s4 < 8; s4++) {
                    float4 ww = qw4[s4];
                    bias += ww.x * sv[s4 * 4] + ww.y * sv[s4 * 4 + 1]
                          + ww.z * sv[s4 * 4 + 2] + ww.w * sv[s4 * 4 + 3];
                }
                float sc = PT[w * PT_Q + lane * 9 + h2] + bias;
                float p = masked ? 0.f : __expf(sc);
                if (h2 == 0) pq0 = p;
                P2[(w * 8 + h2) * P2R + lane] = p;
            }
            scores0[((size_t)(b * LSEQ + q0 + w)) * LSEQ + k0 + lane] = pq0;
        }
        __syncthreads();   // (2) p visible; PT reads done (safe for next QK)

        // prefetch next struct slice into registers (hidden under ACC work)
        if (kt + 1 < NKT) {
            const float2* src = reinterpret_cast<const float2*>(st_qrow + (size_t)(k0 + TK) * DS);
#pragma unroll
            for (int i = 0; i < 15; i++) pre[i] = src[i * 32 + lane];
        }

        // ======== ACC-V: warp = head w, lane = (aq, aoct) ========
        {
            const float* vbase = vh + ((size_t)(b * LSEQ + k0)) * DM + w * DH + aoct * 8;
            const float* prow = &P2[(aq * 8 + w) * P2R];
#pragma unroll 4
            for (int k = 0; k < TK; k++) {
                float p = prow[k];
                float4 v0 = *reinterpret_cast<const float4*>(vbase + (size_t)k * DM);
                float4 v1 = *reinterpret_cast<const float4*>(vbase + (size_t)k * DM + 4);
                acc[0] += p * v0.x; acc[1] += p * v0.y; acc[2] += p * v0.z; acc[3] += p * v0.w;
                acc[4] += p * v1.x; acc[5] += p * v1.y; acc[6] += p * v1.z; acc[7] += p * v1.w;
                lsum += p;
            }
        }

        // ======== ACC-PS: warp = q-row w, lane = s (own P2 rows, own ST row) ==
        {
            const float* stq2 = ST + w * ST_Q + lane;
            const float* pbase = &P2[(w * 8) * P2R];
#pragma unroll 4
            for (int k = 0; k < TK; k++) {
                float svk = stq2[k * ST_K];
#pragma unroll
                for (int h2 = 0; h2 < NH; h2++)
                    psp[h2] += pbase[h2 * P2R + k] * svk;
            }
        }

        // commit prefetched struct tile — own warp's row, NO barrier needed
        if (kt + 1 < NKT) {
            int kk = ek0, ss = es0;
#pragma unroll
            for (int i = 0; i < 15; i++) {
                st_dst[kk * ST_K + ss] = pre[i].x;
                int k2 = kk, s2 = ss + 1;
                if (s2 == DS) { s2 = 0; k2++; }
                st_dst[k2 * ST_K + s2] = pre[i].y;
                ss += 4; kk += 2;
                if (ss >= DS) { ss -= DS; kk++; }
            }
        }
        // no third barrier: all cross-warp hazards covered by syncs (1) and (2)
    }

    // ---- epilogue ----
    if (aoct == 0) LS[aq * 9 + w] = lsum;        // lsum for (h=w, q=aq)
    if (lane < DS) {
#pragma unroll
        for (int h2 = 0; h2 < NH; h2++)
            PS[(w * 8 + h2) * P2R + lane] = psp[h2];   // ps for (q=w, h2, s=lane)
    }
    __syncthreads();

    // final: warp = head w, lane = (aq, aoct)
    {
        float linv = 1.f / LS[aq * 9 + w];
        float c[8];
#pragma unroll
        for (int j = 0; j < 8; j++) c[j] = acc[j];

        const float* psrow = &PS[(aq * 8 + w) * P2R];
#pragma unroll
        for (int s = 0; s < DS; s++) {
            float pv = psrow[s];
            const float* wr = &WSV[s * 33 + aoct * 8];
#pragma unroll
            for (int j = 0; j < 8; j++) c[j] += pv * wr[j];
        }
#pragma unroll
        for (int j = 0; j < 8; j++) c[j] = c[j] * linv + bsv[aoct * 8 + j];

        float* outp = &ctx[((size_t)(b * LSEQ + q0 + aq)) * DM + w * DH + aoct * 8];
        float4 o0 = { c[0], c[1], c[2], c[3] };
        float4 o1 = { c[4], c[5], c[6], c[7] };
        reinterpret_cast<float4*>(outp)[0] = o0;
        reinterpret_cast<float4*>(outp)[1] = o1;
    }
}

// ---------------------------------------------------------------------------
__global__ void __launch_bounds__(256) normalize_rows(
    const float* __restrict__ P, float* __restrict__ O)
{
    const int row = blockIdx.x;
    const float* s = P + (size_t)row * LSEQ;
    float* o = O + (size_t)row * LSEQ;
    const int t = threadIdx.x;

    float a = s[t], b = s[t + 256];
    float sum = a + b;
    __shared__ float red[8];
#pragma unroll
    for (int off = 16; off; off >>= 1) sum += __shfl_xor_sync(0xffffffffu, sum, off);
    if ((t & 31) == 0) red[t >> 5] = sum;
    __syncthreads();
    float sAll = 0.f;
#pragma unroll
    for (int i = 0; i < 8; i++) sAll += red[i];
    float inv = 1.f / sAll;
    o[t] = a * inv;
    o[t + 256] = b * inv;
}

// ---------------------------------------------------------------------------
extern "C" void kernel_launch(void* const* d_in, const int* in_sizes, int n_in,
                              void* d_out, int out_size)
{
    const float* key   = (const float*)d_in[0];
    const float* value = (const float*)d_in[1];
    const float* query = (const float*)d_in[2];

    const float* structure;
    const void*  kmaskp;
    if (in_sizes[3] == BSZ * LSEQ) {
        kmaskp    = d_in[3];
        structure = (const float*)d_in[4];
    } else {
        structure = (const float*)d_in[3];
        kmaskp    = d_in[4];
    }

    const float* wq  = (const float*)d_in[5];
    const float* bq  = (const float*)d_in[6];
    const float* wk  = (const float*)d_in[7];
    const float* bk  = (const float*)d_in[8];
    const float* wv  = (const float*)d_in[9];
    const float* bv  = (const float*)d_in[10];
    const float* wsk = (const float*)d_in[11];
    // d_in[12] = bsk: softmax-invariant, dropped.
    const float* wsv = (const float*)d_in[13];
    const float* bsv = (const float*)d_in[14];
    const float* wf  = (const float*)d_in[15];
    const float* bf  = (const float*)d_in[16];

    float* out = (float*)d_out;
    float* fin = out + (size_t)BSZ * LSEQ * DM;

    float* scratch = nullptr;
    cudaGetSymbolAddress((void**)&scratch, g_scratch);
    float* qh  = scratch;
    float* kh  = qh + (size_t)BSZ * LSEQ * DM;
    float* vh  = kh + (size_t)BSZ * LSEQ * DM;
    float* ctx = vh + (size_t)BSZ * LSEQ * DM;
    float* ktr = ctx + (size_t)BSZ * LSEQ * DM;
    float* sc0 = ktr + (size_t)BSZ * LSEQ * DM;

    detect_mask_kernel<<<1, 256>>>((const unsigned char*)kmaskp, BSZ * LSEQ);

    qkv_gemm<<<dim3(2, 32, 3), 256>>>(query, key, value,
                                      wq, wk, wv, bq, bk, bv,
                                      qh, kh, vh);

    transpose_k<<<dim3(16, 8, 8), dim3(32, 8)>>>(kh, ktr);

    cudaFuncSetAttribute(attn_kernel, cudaFuncAttributeMaxDynamicSharedMemorySize, SMEM_BYTES);
    attn_kernel<<<BSZ * (LSEQ / TQ), NTHREADS, SMEM_BYTES>>>(
        qh, ktr, vh, structure, kmaskp, wsk, wsv, bsv, ctx, sc0);

    normalize_rows<<<BSZ * LSEQ, 256>>>(sc0, fin);
    gemm128<<<dim3(2, 32), 256>>>(ctx, wf, bf, out, 1.0f);
}